// round 16
// baseline (speedup 1.0000x reference)
#include <cuda_runtime.h>
#include <cuda_fp16.h>
#include <math.h>
#include <stdint.h>

#define NC 200000
#define NF 64
#define NH 128
#define NS 512

#define CHUNK 2048
#define NCHUNK 98          // ceil(NC / CHUNK)
#define NMLP 1563          // ceil(NC / 128)
#define NDEN (NCHUNK * 8)  // 784
#define DTPB 256

// ---- scratch ----
__device__ float    d_logits[NC];
__device__ float    d_w2k[NH];
__device__ uint32_t d_W1frag[NF * NH / 2];  // W1 as f16x2, MMA-fragment order (16 KB)
__device__ float    d_c2;
__device__ float    d_sums[NS];
__device__ float    d_sl[NS];
__device__ float    d_cntf[NS];
__device__ unsigned d_ticket;
__device__ int      d_chunkcnt[NCHUNK];

__device__ __forceinline__ uint32_t packh2(float a, float b) {
    __half2 h = __floats2half2_rn(a, b);
    return *(uint32_t*)&h;
}

__device__ __forceinline__ void mma_f16(float c[4], const uint32_t a[4],
                                        uint32_t b0, uint32_t b1) {
    asm volatile(
        "mma.sync.aligned.m16n8k16.row.col.f32.f16.f16.f32 "
        "{%0,%1,%2,%3}, {%4,%5,%6,%7}, {%8,%9}, {%0,%1,%2,%3};"
        : "+f"(c[0]), "+f"(c[1]), "+f"(c[2]), "+f"(c[3])
        : "r"(a[0]), "r"(a[1]), "r"(a[2]), "r"(a[3]), "r"(b0), "r"(b1));
}

// ---- launch 0: prep (W1 f16 frag pack, w2k fold, accum init, c2, flags) ----
__global__ void k_prep(const float* __restrict__ W1, const float* __restrict__ W2,
                       const float* __restrict__ b2, const float* __restrict__ kw) {
    int b = blockIdx.x;
    int tid = threadIdx.x;  // 128
    if (b < 16) {
        if (tid < 64) {
            int h = tid >> 5, lane = tid & 31;
            int q = lane & 3, g = lane >> 2;
            int col = b * 8 + g;
            int k0 = 32 * h;
            uint4 v;
            v.x = packh2(W1[(k0 + 2 * q) * NH + col],      W1[(k0 + 2 * q + 1) * NH + col]);
            v.y = packh2(W1[(k0 + 2 * q + 8) * NH + col],  W1[(k0 + 2 * q + 9) * NH + col]);
            v.z = packh2(W1[(k0 + 16 + 2 * q) * NH + col], W1[(k0 + 17 + 2 * q) * NH + col]);
            v.w = packh2(W1[(k0 + 24 + 2 * q) * NH + col], W1[(k0 + 25 + 2 * q) * NH + col]);
            ((uint4*)d_W1frag)[(b * 2 + h) * 32 + lane] = v;
        }
    } else if (b < 32) {
        int w = tid >> 5, l = tid & 31;
        int rbase = (b - 16) * 8 + w * 2;
#pragma unroll
        for (int rr = 0; rr < 2; rr++) {
            int h = rbase + rr;
            float s = W2[h * NH + l] * kw[l] + W2[h * NH + l + 32] * kw[l + 32] +
                      W2[h * NH + l + 64] * kw[l + 64] + W2[h * NH + l + 96] * kw[l + 96];
            for (int o = 16; o; o >>= 1) s += __shfl_xor_sync(0xffffffffu, s, o);
            if (l == 0) d_w2k[h] = s;
        }
    } else if (b < 36) {
        int i = (b - 32) * 128 + tid;
        d_sums[i] = 0.f; d_sl[i] = 0.f; d_cntf[i] = 0.f;
        if (i < NCHUNK) d_chunkcnt[i] = 0;
    } else {
        float c = (tid < NH) ? b2[tid] * kw[tid] : 0.f;
        for (int o = 16; o; o >>= 1) c += __shfl_xor_sync(0xffffffffu, c, o);
        __shared__ float red[4];
        if ((tid & 31) == 0) red[tid >> 5] = c;
        __syncthreads();
        if (tid == 0) {
            d_c2 = red[0] + red[1] + red[2] + red[3];
            d_ticket = 0u;
        }
    }
}

// ================== launch 1: fused mlp-producer + denom-consumer ==================
#define HST 72
#define OFF_FEAT 0
#define OFF_B1   (128 * HST * 2)
#define OFF_WK   (OFF_B1 + 512)
// denom view of the same smem
#define OFF_ES   0
#define OFF_PVS  (CHUNK * 4)
#define OFF_PCS  (CHUNK * 8)
#define SMEM_MAIN (CHUNK * 12 + 64)

__global__ void __launch_bounds__(256, 5) k_main(const float* __restrict__ feat,
                                                 const float* __restrict__ b1,
                                                 const int* __restrict__ sel,
                                                 const int* __restrict__ proof,
                                                 float* __restrict__ out) {
    extern __shared__ char smem[];
    int tid = threadIdx.x;
    int wid = tid >> 5, lane = tid & 31;
    int g = lane >> 2, q = lane & 3;

    if (blockIdx.x < NMLP) {
        // ================= producer: fp16 m16n8k16 MLP, 128 clauses =================
        __half* featS = (__half*)(smem + OFF_FEAT);
        float*  b1s   = (float*)(smem + OFF_B1);
        float*  wks   = (float*)(smem + OFF_WK);
        int base = blockIdx.x * 128;

        for (int i = tid; i < 128 * 16; i += 256) {
            int row = i >> 4, f4 = i & 15;
            float4 v = make_float4(0.f, 0.f, 0.f, 0.f);
            int c = base + row;
            if (c < NC) v = *(const float4*)(feat + (size_t)c * NF + f4 * 4);
            uint2 hv;
            hv.x = packh2(v.x, v.y);
            hv.y = packh2(v.z, v.w);
            *(uint2*)(featS + row * HST + f4 * 4) = hv;
        }
        if (tid < NH) { b1s[tid] = b1[tid]; wks[tid] = d_w2k[tid]; }
        __syncthreads();

        uint32_t a[4][4];
        int r0 = wid * 16 + g;
#pragma unroll
        for (int kt = 0; kt < 4; kt++) {
            int kb = kt * 16;
            a[kt][0] = *(const uint32_t*)(featS + r0 * HST + kb + 2 * q);
            a[kt][1] = *(const uint32_t*)(featS + (r0 + 8) * HST + kb + 2 * q);
            a[kt][2] = *(const uint32_t*)(featS + r0 * HST + kb + 2 * q + 8);
            a[kt][3] = *(const uint32_t*)(featS + (r0 + 8) * HST + kb + 2 * q + 8);
        }

        const uint4* fragp = (const uint4*)d_W1frag + lane;
        float acc0 = 0.f, acc1 = 0.f;
#pragma unroll
        for (int nt = 0; nt < 16; nt++) {
            uint4 F0 = fragp[(nt * 2 + 0) * 32];
            uint4 F1 = fragp[(nt * 2 + 1) * 32];
            float c0[4] = {0.f, 0.f, 0.f, 0.f};
            mma_f16(c0, a[0], F0.x, F0.y);
            mma_f16(c0, a[1], F0.z, F0.w);
            mma_f16(c0, a[2], F1.x, F1.y);
            mma_f16(c0, a[3], F1.z, F1.w);
            int col0 = nt * 8 + 2 * q, col1 = col0 + 1;
            float bb0 = b1s[col0], bb1 = b1s[col1];
            float wk0 = wks[col0], wk1 = wks[col1];
            acc0 += fmaxf(c0[0] + bb0, 0.f) * wk0 + fmaxf(c0[1] + bb1, 0.f) * wk1;
            acc1 += fmaxf(c0[2] + bb0, 0.f) * wk0 + fmaxf(c0[3] + bb1, 0.f) * wk1;
        }

        float c2v = d_c2;
#pragma unroll
        for (int rh = 0; rh < 2; rh++) {
            float v = (rh == 0) ? acc0 : acc1;
            v += __shfl_xor_sync(0xffffffffu, v, 1);
            v += __shfl_xor_sync(0xffffffffu, v, 2);
            v += c2v;
            int c = base + wid * 16 + rh * 8 + g;
            if (c < NC && q == 0) d_logits[c] = v;
        }
        // publish: this block's 128 logits are done
        __syncthreads();
        if (tid == 0) {
            __threadfence();
            atomicAdd(&d_chunkcnt[blockIdx.x >> 4], 1);
        }
        return;
    }

    // ================= consumer: fused denom + numer + count =================
    float* es  = (float*)(smem + OFF_ES);
    float* pvs = (float*)(smem + OFF_PVS);
    float* pcs = (float*)(smem + OFF_PCS);
    __shared__ int lastflag;

    int dbid = blockIdx.x - NMLP;
    int cx = dbid >> 3;        // chunk (low chunks first -> ready earliest)
    int cy = dbid & 7;         // step group
    int base = cx * CHUNK;
    int w = wid, l = lane;

    // wait for this chunk's producers (+chunk 0 for the shift)
    if (tid == 0) {
        int need = (cx == NCHUNK - 1) ? (NMLP - (NCHUNK - 1) * 16) : 16;
        volatile int* cc = d_chunkcnt;
        while (cc[cx] < need || cc[0] < 16) __nanosleep(200);
        lastflag = 0;
    }
    __syncthreads();
    __threadfence();
    float shift = d_logits[0];

    for (int i = tid; i < CHUNK; i += DTPB) {
        int n = base + i;
        float e = 0.f, pv = 0.f, pc = 0.f;
        if (n < NC) {
            float lg = d_logits[n];
            e = expf(lg - shift);
            if (proof[n]) { pv = lg; pc = 1.f; }
        }
        es[i] = e; pvs[i] = pv; pcs[i] = pc;
    }
    __syncthreads();

    bool fast = (base + CHUNK) <= NC;
    for (int si = 0; si < 8; si++) {
        int s = cy * 64 + si * 8 + w;
        const int* mrow = sel + (size_t)s * NC + base;
        float ad = 0.f, an = 0.f, ac = 0.f;
        if (fast) {
            const int4* m4 = (const int4*)mrow;
#pragma unroll
            for (int j = 0; j < 16; j++) {
                int p = j * 32 + l;
                int4 m = m4[p];
                float4 e4 = *(const float4*)&es[p * 4];
                float4 v4 = *(const float4*)&pvs[p * 4];
                float4 q4 = *(const float4*)&pcs[p * 4];
                if (m.x) { ad += e4.x; an += v4.x; ac += q4.x; }
                if (m.y) { ad += e4.y; an += v4.y; ac += q4.y; }
                if (m.z) { ad += e4.z; an += v4.z; ac += q4.z; }
                if (m.w) { ad += e4.w; an += v4.w; ac += q4.w; }
            }
        } else {
            for (int j = 0; j < 16; j++) {
                int e0 = j * 128 + l * 4;
#pragma unroll
                for (int p = 0; p < 4; p++) {
                    int n = base + e0 + p;
                    if (n < NC && mrow[e0 + p]) {
                        ad += es[e0 + p]; an += pvs[e0 + p]; ac += pcs[e0 + p];
                    }
                }
            }
        }
        for (int o = 16; o; o >>= 1) {
            ad += __shfl_xor_sync(0xffffffffu, ad, o);
            an += __shfl_xor_sync(0xffffffffu, an, o);
            ac += __shfl_xor_sync(0xffffffffu, ac, o);
        }
        if (l == 0) {
            atomicAdd(&d_sums[s], ad);
            atomicAdd(&d_sl[s], an);
            atomicAdd(&d_cntf[s], ac);
        }
    }

    // ---- last consumer computes the final loss ----
    if (tid == 0) {
        __threadfence();
        unsigned t = atomicAdd(&d_ticket, 1u);
        lastflag = (t == (unsigned)(NDEN - 1));
    }
    __syncthreads();
    if (lastflag) {
        float v = 0.f;
#pragma unroll
        for (int r = 0; r < 2; r++) {
            int s = tid + r * 256;
            v += (shift + logf(d_sums[s])) - d_sl[s] / d_cntf[s];
        }
        for (int o = 16; o; o >>= 1) v += __shfl_xor_sync(0xffffffffu, v, o);
        __shared__ float red[8];
        if (l == 0) red[w] = v;
        __syncthreads();
        if (tid == 0) {
            float tot = 0.f;
#pragma unroll
            for (int wv = 0; wv < 8; wv++) tot += red[wv];
            out[0] = tot / (float)NS;
        }
    }
}

extern "C" void kernel_launch(void* const* d_in, const int* in_sizes, int n_in,
                              void* d_out, int out_size) {
    const float* feat = (const float*)d_in[0];
    const float* W1   = (const float*)d_in[1];
    const float* b1   = (const float*)d_in[2];
    const float* W2   = (const float*)d_in[3];
    const float* b2   = (const float*)d_in[4];
    const float* kw   = (const float*)d_in[5];
    const int*   sel  = (const int*)d_in[6];
    const int*   proof= (const int*)d_in[7];
    float* out = (float*)d_out;

    static int smem_set = 0;
    if (!smem_set) {
        cudaFuncSetAttribute(k_main, cudaFuncAttributeMaxDynamicSharedMemorySize, SMEM_MAIN);
        smem_set = 1;
    }

    k_prep<<<37, 128>>>(W1, W2, b2, kw);                            // 0
    k_main<<<NMLP + NDEN, 256, SMEM_MAIN>>>(feat, b1, sel, proof, out);  // 1
}

// round 17
// speedup vs baseline: 1.1420x; 1.1420x over previous
#include <cuda_runtime.h>
#include <cuda_fp16.h>
#include <math.h>
#include <stdint.h>

#define NC 200000
#define NF 64
#define NH 128
#define NS 512

// ---- scratch ----
__device__ float    d_logits[NC];
__device__ float    d_w2k[NH];
__device__ uint32_t d_W1frag[NF * NH / 2];  // W1 as f16x2, MMA-fragment order (16 KB)
__device__ float    d_c2;
__device__ float    d_sums[NS];
__device__ float    d_sl[NS];
__device__ float    d_cntf[NS];
__device__ unsigned d_ticket;

__device__ __forceinline__ uint32_t packh2(float a, float b) {
    __half2 h = __floats2half2_rn(a, b);
    return *(uint32_t*)&h;
}

__device__ __forceinline__ void mma_f16(float c[4], const uint32_t a[4],
                                        uint32_t b0, uint32_t b1) {
    asm volatile(
        "mma.sync.aligned.m16n8k16.row.col.f32.f16.f16.f32 "
        "{%0,%1,%2,%3}, {%4,%5,%6,%7}, {%8,%9}, {%0,%1,%2,%3};"
        : "+f"(c[0]), "+f"(c[1]), "+f"(c[2]), "+f"(c[3])
        : "r"(a[0]), "r"(a[1]), "r"(a[2]), "r"(a[3]), "r"(b0), "r"(b1));
}

// ---- launch 0: prep (W1 f16 frag pack, w2k fold, accum init, c2, ticket) ----
__global__ void k_prep(const float* __restrict__ W1, const float* __restrict__ W2,
                       const float* __restrict__ b2, const float* __restrict__ kw) {
    int b = blockIdx.x;
    int tid = threadIdx.x;  // 128
    if (b < 16) {
        if (tid < 64) {
            int h = tid >> 5, lane = tid & 31;
            int q = lane & 3, g = lane >> 2;
            int col = b * 8 + g;
            int k0 = 32 * h;
            uint4 v;
            v.x = packh2(W1[(k0 + 2 * q) * NH + col],      W1[(k0 + 2 * q + 1) * NH + col]);
            v.y = packh2(W1[(k0 + 2 * q + 8) * NH + col],  W1[(k0 + 2 * q + 9) * NH + col]);
            v.z = packh2(W1[(k0 + 16 + 2 * q) * NH + col], W1[(k0 + 17 + 2 * q) * NH + col]);
            v.w = packh2(W1[(k0 + 24 + 2 * q) * NH + col], W1[(k0 + 25 + 2 * q) * NH + col]);
            ((uint4*)d_W1frag)[(b * 2 + h) * 32 + lane] = v;
        }
    } else if (b < 32) {
        int w = tid >> 5, l = tid & 31;
        int rbase = (b - 16) * 8 + w * 2;
#pragma unroll
        for (int rr = 0; rr < 2; rr++) {
            int h = rbase + rr;
            float s = W2[h * NH + l] * kw[l] + W2[h * NH + l + 32] * kw[l + 32] +
                      W2[h * NH + l + 64] * kw[l + 64] + W2[h * NH + l + 96] * kw[l + 96];
            for (int o = 16; o; o >>= 1) s += __shfl_xor_sync(0xffffffffu, s, o);
            if (l == 0) d_w2k[h] = s;
        }
    } else if (b < 36) {
        int i = (b - 32) * 128 + tid;
        d_sums[i] = 0.f; d_sl[i] = 0.f; d_cntf[i] = 0.f;
    } else {
        float c = (tid < NH) ? b2[tid] * kw[tid] : 0.f;
        for (int o = 16; o; o >>= 1) c += __shfl_xor_sync(0xffffffffu, c, o);
        __shared__ float red[4];
        if ((tid & 31) == 0) red[tid >> 5] = c;
        __syncthreads();
        if (tid == 0) {
            d_c2 = red[0] + red[1] + red[2] + red[3];
            d_ticket = 0u;
        }
    }
}

// ================== launch 1: fp16 m16n8k16 MLP ==================
#define HST 72
#define OFF_FEAT 0
#define OFF_B1   (128 * HST * 2)
#define OFF_WK   (OFF_B1 + 512)
#define SMEM_MLP (OFF_WK + 512)

__global__ void __launch_bounds__(256, 5) k_mlp(const float* __restrict__ feat,
                                                const float* __restrict__ b1) {
    extern __shared__ char smem[];
    __half* featS = (__half*)(smem + OFF_FEAT);
    float*  b1s   = (float*)(smem + OFF_B1);
    float*  wks   = (float*)(smem + OFF_WK);

    int tid = threadIdx.x;
    int wid = tid >> 5, lane = tid & 31;
    int g = lane >> 2, q = lane & 3;
    int base = blockIdx.x * 128;

    for (int i = tid; i < 128 * 16; i += 256) {
        int row = i >> 4, f4 = i & 15;
        float4 v = make_float4(0.f, 0.f, 0.f, 0.f);
        int c = base + row;
        if (c < NC) v = *(const float4*)(feat + (size_t)c * NF + f4 * 4);
        uint2 hv;
        hv.x = packh2(v.x, v.y);
        hv.y = packh2(v.z, v.w);
        *(uint2*)(featS + row * HST + f4 * 4) = hv;
    }
    if (tid < NH) { b1s[tid] = b1[tid]; wks[tid] = d_w2k[tid]; }
    __syncthreads();

    uint32_t a[4][4];
    int r0 = wid * 16 + g;
#pragma unroll
    for (int kt = 0; kt < 4; kt++) {
        int kb = kt * 16;
        a[kt][0] = *(const uint32_t*)(featS + r0 * HST + kb + 2 * q);
        a[kt][1] = *(const uint32_t*)(featS + (r0 + 8) * HST + kb + 2 * q);
        a[kt][2] = *(const uint32_t*)(featS + r0 * HST + kb + 2 * q + 8);
        a[kt][3] = *(const uint32_t*)(featS + (r0 + 8) * HST + kb + 2 * q + 8);
    }

    const uint4* fragp = (const uint4*)d_W1frag + lane;
    float acc0 = 0.f, acc1 = 0.f;
#pragma unroll
    for (int nt = 0; nt < 16; nt++) {
        uint4 F0 = fragp[(nt * 2 + 0) * 32];
        uint4 F1 = fragp[(nt * 2 + 1) * 32];
        float c0[4] = {0.f, 0.f, 0.f, 0.f};
        mma_f16(c0, a[0], F0.x, F0.y);
        mma_f16(c0, a[1], F0.z, F0.w);
        mma_f16(c0, a[2], F1.x, F1.y);
        mma_f16(c0, a[3], F1.z, F1.w);
        int col0 = nt * 8 + 2 * q, col1 = col0 + 1;
        float bb0 = b1s[col0], bb1 = b1s[col1];
        float wk0 = wks[col0], wk1 = wks[col1];
        acc0 += fmaxf(c0[0] + bb0, 0.f) * wk0 + fmaxf(c0[1] + bb1, 0.f) * wk1;
        acc1 += fmaxf(c0[2] + bb0, 0.f) * wk0 + fmaxf(c0[3] + bb1, 0.f) * wk1;
    }

    float c2v = d_c2;
#pragma unroll
    for (int rh = 0; rh < 2; rh++) {
        float v = (rh == 0) ? acc0 : acc1;
        v += __shfl_xor_sync(0xffffffffu, v, 1);
        v += __shfl_xor_sync(0xffffffffu, v, 2);
        v += c2v;
        int c = base + wid * 16 + rh * 8 + g;
        if (c < NC && q == 0) d_logits[c] = v;
    }
}

// ---- launch 2: fused denom + numerator + count + (last block) final loss ----
#define CHUNK 2048
#define DTPB 256
#define NBLK ((NC + CHUNK - 1) / CHUNK * (NS / 64))
__global__ void __launch_bounds__(DTPB) k_denom(const int* __restrict__ sel,
                                                const int* __restrict__ proof,
                                                float* __restrict__ out) {
    __shared__ float es[CHUNK];
    __shared__ float pvs[CHUNK];
    __shared__ float pcs[CHUNK];
    __shared__ int lastflag;
    int tid = threadIdx.x;
    int w = tid >> 5, l = tid & 31;
    int base = blockIdx.x * CHUNK;
    float shift = d_logits[0];

    for (int i = tid; i < CHUNK; i += DTPB) {
        int n = base + i;
        float e = 0.f, pv = 0.f, pc = 0.f;
        if (n < NC) {
            float lg = d_logits[n];
            e = __expf(lg - shift);
            if (proof[n]) { pv = lg; pc = 1.f; }
        }
        es[i] = e; pvs[i] = pv; pcs[i] = pc;
    }
    __syncthreads();

    bool fast = (base + CHUNK) <= NC;
    for (int si = 0; si < 8; si++) {
        int s = blockIdx.y * 64 + si * 8 + w;
        const int* mrow = sel + (size_t)s * NC + base;
        float ad = 0.f, an = 0.f, ac = 0.f;
        if (fast) {
            const int4* m4 = (const int4*)mrow;
#pragma unroll
            for (int j = 0; j < 16; j++) {
                int p = j * 32 + l;
                int4 m = m4[p];
                float4 e4 = *(const float4*)&es[p * 4];
                float4 v4 = *(const float4*)&pvs[p * 4];
                float4 q4 = *(const float4*)&pcs[p * 4];
                if (m.x) { ad += e4.x; an += v4.x; ac += q4.x; }
                if (m.y) { ad += e4.y; an += v4.y; ac += q4.y; }
                if (m.z) { ad += e4.z; an += v4.z; ac += q4.z; }
                if (m.w) { ad += e4.w; an += v4.w; ac += q4.w; }
            }
        } else {
            for (int j = 0; j < 16; j++) {
                int e0 = j * 128 + l * 4;
#pragma unroll
                for (int p = 0; p < 4; p++) {
                    int n = base + e0 + p;
                    if (n < NC && mrow[e0 + p]) {
                        ad += es[e0 + p]; an += pvs[e0 + p]; ac += pcs[e0 + p];
                    }
                }
            }
        }
        for (int o = 16; o; o >>= 1) {
            ad += __shfl_xor_sync(0xffffffffu, ad, o);
            an += __shfl_xor_sync(0xffffffffu, an, o);
            ac += __shfl_xor_sync(0xffffffffu, ac, o);
        }
        if (l == 0) {
            atomicAdd(&d_sums[s], ad);
            atomicAdd(&d_sl[s], an);
            atomicAdd(&d_cntf[s], ac);
        }
    }

    // ---- last-block-done: compute the final loss inline ----
    if (tid == 0) {
        __threadfence();
        unsigned t = atomicAdd(&d_ticket, 1u);
        lastflag = (t == NBLK - 1u);
    }
    __syncthreads();
    if (lastflag) {
        float v = 0.f;
#pragma unroll
        for (int r = 0; r < 2; r++) {
            int s = tid + r * 256;
            v += (shift + logf(d_sums[s])) - d_sl[s] / d_cntf[s];
        }
        for (int o = 16; o; o >>= 1) v += __shfl_xor_sync(0xffffffffu, v, o);
        __shared__ float red[8];
        if (l == 0) red[w] = v;
        __syncthreads();
        if (tid == 0) {
            float tot = 0.f;
#pragma unroll
            for (int wv = 0; wv < 8; wv++) tot += red[wv];
            out[0] = tot / (float)NS;
        }
    }
}

extern "C" void kernel_launch(void* const* d_in, const int* in_sizes, int n_in,
                              void* d_out, int out_size) {
    const float* feat = (const float*)d_in[0];
    const float* W1   = (const float*)d_in[1];
    const float* b1   = (const float*)d_in[2];
    const float* W2   = (const float*)d_in[3];
    const float* b2   = (const float*)d_in[4];
    const float* kw   = (const float*)d_in[5];
    const int*   sel  = (const int*)d_in[6];
    const int*   proof= (const int*)d_in[7];
    float* out = (float*)d_out;

    static int smem_set = 0;
    if (!smem_set) {
        cudaFuncSetAttribute(k_mlp, cudaFuncAttributeMaxDynamicSharedMemorySize, SMEM_MLP);
        smem_set = 1;
    }

    k_prep<<<37, 128>>>(W1, W2, b2, kw);                   // 0
    k_mlp<<<(NC + 127) / 128, 256, SMEM_MLP>>>(feat, b1);  // 1
    dim3 dg((NC + CHUNK - 1) / CHUNK, NS / 64);
    k_denom<<<dg, DTPB>>>(sel, proof, out);                // 2
}